// round 14
// baseline (speedup 1.0000x reference)
#include <cuda_runtime.h>
#include <cuda_fp16.h>
#include <mma.h>
#include <cstdint>

using namespace nvcuda;

#define B_   256
#define K_   256
#define C_   128
#define KG_  64
#define OUTC 117
#define OCH  183

// scratch (allocation-free rule: __device__ globals)
__device__ float g_net1[B_ * C_ * K_];   // layer1 output, no bias (B,128,256)
__device__ float g_net2[B_ * C_ * K_];   // layer2 output, no bias
__device__ float g_s[2][C_];             // BN sum accumulators
__device__ float g_s2[2][C_];            // BN sum-of-squares accumulators
__device__ __half g_W1h[C_ * 2 * C_];    // fp16 W1 [128][256]
__device__ __half g_W2h[C_ * C_];        // fp16 W2 [128][128]
__device__ __half g_W3h[C_ * C_];        // fp16 W3 [128][128] (rows 117.. zero)

// ===========================================================================
// prep: weight fp16 conversion + objectness_label + get_index + zero stats
// grid = B_ (256 blocks), block = 256 threads; block b converts weight
// elements [b*256, b*256+256).
// ===========================================================================
__global__ void prep_kernel(const float* __restrict__ xyz,
                            const float* __restrict__ gt,
                            const int* __restrict__ pred,
                            const float* __restrict__ W1,
                            const float* __restrict__ W2,
                            const float* __restrict__ W3,
                            float* __restrict__ lbl,
                            float* __restrict__ idxo,
                            float* __restrict__ sum1) {
    int b = blockIdx.x, k = threadIdx.x;

    // ---- weight conversion: 1 element per thread ----
    {
        int i = b * 256 + k;
        if (i < 32768) {
            g_W1h[i] = __float2half_rn(W1[i]);
        } else if (i < 49152) {
            g_W2h[i - 32768] = __float2half_rn(W2[i - 32768]);
        } else {
            int j = i - 49152;
            int row = j >> 7;
            g_W3h[j] = (row < OUTC) ? __float2half_rn(W3[row * C_ + (j & 127)])
                                    : __float2half_rn(0.f);
        }
    }
    if (b == 0 && k < C_) {
        g_s[0][k] = 0.f; g_s[1][k] = 0.f;
        g_s2[0][k] = 0.f; g_s2[1][k] = 0.f;
    }

    // ---- label ----
    __shared__ float sg[KG_ * 3];
    if (k < KG_ * 3) sg[k] = gt[b * KG_ * 3 + k];
    __syncthreads();
    const float* p = xyz + (b * K_ + k) * 3;
    float x = p[0], y = p[1], z = p[2];
    float mn = 1e30f;
#pragma unroll 8
    for (int g = 0; g < KG_; g++) {
        float dx = x - sg[g * 3 + 0];
        float dy = y - sg[g * 3 + 1];
        float dz = z - sg[g * 3 + 2];
        mn = fminf(mn, dx * dx + dy * dy + dz * dz);
    }
    lbl[b * K_ + k] = (sqrtf(mn + 1e-6f) < 0.3f) ? 1.0f : 0.0f;

    // ---- index (pred is int32: JAX x64 disabled) ----
    int pv = pred[b * K_ + k];
    __shared__ int sc[K_];
    __shared__ int res[K_];
    sc[k] = pv;
    res[k] = k;
    __syncthreads();
    for (int off = 1; off < K_; off <<= 1) {
        int add = (k >= off) ? sc[k - off] : 0;
        __syncthreads();
        sc[k] += add;
        __syncthreads();
    }
    int num = sc[K_ - 1];
    int excl = sc[k] - pv;
    if (pv == 1) res[excl] = k;
    __syncthreads();
    idxo[b * K_ + k] = (float)((k < num) ? res[k] : k);
    if (k == 0) sum1[b] = (float)num;
}

// ===========================================================================
// wmma fp16 GEMM (fp32 accum): Y[b,m,n] = sum_c W[m,c]*X[b,c,n]
// (no bias in GEMM1/2 — BN cancels channel shifts exactly; b3 applied in ASM)
// FULL-K staging: Bsh holds a 128x128 B tile (one chunk); CIN=256 runs two
// chunks (chunk0 = X0/features, chunk1 = X1/rn). One sync pair per chunk;
// mma phase is 8 uninterrupted k-steps. A frags from global fp16 W (L1).
// FIN  : compute folded BN (a,d) per-CTA from g_s/g_s2 at kernel start.
// STATS: fused per-channel sum/sum^2 via shfl + atomics.
// ASM  : fuse 183-channel output assembly (bias b3 + scale + xyz).
// grid = (2 n-halves, B_), 256 threads (8 warps), warp tile 32x64, 2 CTA/SM.
// ===========================================================================
#define BLDH 136   // Bs leading dim in halves (272B rows; conflict-light)
#define DLD  68
// smem: Bsh 128*136*2 = 34816 B (aliased by Dsm 128*68*4 = 34816 B)
//       sA 512 B | sD 512 B | sms 216+ | sbias 468 -> total 36544
#define SMEM_BYTES 36544

template <int CIN, int FIN, int STATS, int ASM>
__global__ void __launch_bounds__(256, 2)
wmma_gemm(const __half* __restrict__ gW, const float* __restrict__ bias,
          const float* __restrict__ X0, const float* __restrict__ X1,
          const float* __restrict__ gam, const float* __restrict__ bet,
          const float* __restrict__ inS, const float* __restrict__ inS2,
          float* __restrict__ Y,
          float* __restrict__ sS, float* __restrict__ sS2,
          const float* __restrict__ xyz, const float* __restrict__ ms) {
    __shared__ __align__(16) char smbuf[SMEM_BYTES];
    __half* Bsh = reinterpret_cast<__half*>(smbuf);        // [128][BLDH]
    float*  Dsm = reinterpret_cast<float*>(smbuf);         // reused [128][DLD]
    float*  sA    = reinterpret_cast<float*>(smbuf + 34816);  // [128]
    float*  sD    = reinterpret_cast<float*>(smbuf + 35328);  // [128]
    float*  sms   = reinterpret_cast<float*>(smbuf + 35840);  // [54]
    float*  sbias = reinterpret_cast<float*>(smbuf + 36056);  // [117]

    int tid = threadIdx.x;
    int w = tid >> 5;
    int b = blockIdx.y;
    int n0 = blockIdx.x * 128;

    int mw = w >> 1;      // 0..3 -> m offset mw*32
    int nw = w & 1;       // 0..1 -> n offset nw*64

    // ---- in-kernel BN finalize: (a,d) from producer stats ----
    if (FIN) {
        if (tid < C_) {
            const float invN = 1.0f / (B_ * K_);
            float mean = inS[tid] * invN;
            float var = inS2[tid] * invN - mean * mean;
            float rstd = rsqrtf(var + 1e-5f);
            float av = rstd * __ldg(gam + tid);
            sA[tid] = av;
            sD[tid] = __ldg(bet + tid) - mean * av;
        }
        __syncthreads();
    }

    wmma::fragment<wmma::accumulator, 16, 16, 16, float> acc[2][4];
#pragma unroll
    for (int i = 0; i < 2; i++)
#pragma unroll
        for (int j = 0; j < 4; j++)
            wmma::fill_fragment(acc[i][j], 0.f);

    // B staging map: 128 rows, 2 threads/row, 64 floats each
    int brow = tid >> 1;
    int bhalf = (tid & 1) * 64;

    const int NCHUNK = CIN / 128;
#pragma unroll
    for (int cc = 0; cc < NCHUNK; cc++) {
        if (cc) __syncthreads();
        // ---- stage B chunk: X[cc*128+brow, n0+bhalf .. +64) ----
        {
            const float* base = (NCHUNK == 2)
                ? ((cc == 0) ? X0 : X1)   // concat along c
                : X0;
            const float* xp = base + b * C_ * K_ + brow * K_ + n0 + bhalf;
            __half* dst = Bsh + brow * BLDH + bhalf;
            float av = 0.f, dv = 0.f;
            if (FIN) { av = sA[brow]; dv = sD[brow]; }
#pragma unroll
            for (int g = 0; g < 2; g++) {          // 2 groups of 32 floats
                float4 v[8];
#pragma unroll
                for (int q = 0; q < 8; q++)
                    v[q] = *reinterpret_cast<const float4*>(xp + g * 32 + q * 4);
                __align__(16) __half2 h[16];
#pragma unroll
                for (int q = 0; q < 8; q++) {
                    if (FIN) {
                        v[q].x = fmaxf(fmaf(v[q].x, av, dv), 0.f);
                        v[q].y = fmaxf(fmaf(v[q].y, av, dv), 0.f);
                        v[q].z = fmaxf(fmaf(v[q].z, av, dv), 0.f);
                        v[q].w = fmaxf(fmaf(v[q].w, av, dv), 0.f);
                    }
                    h[2 * q]     = __floats2half2_rn(v[q].x, v[q].y);
                    h[2 * q + 1] = __floats2half2_rn(v[q].z, v[q].w);
                }
                uint4* db = reinterpret_cast<uint4*>(dst + g * 32);
                const uint4* sb = reinterpret_cast<const uint4*>(h);
#pragma unroll
                for (int r = 0; r < 4; r++) db[r] = sb[r];
            }
        }
        __syncthreads();

        // ---- one long mma phase: 8 k-steps ----
#pragma unroll
        for (int ks = 0; ks < 8; ks++) {
            wmma::fragment<wmma::matrix_a, 16, 16, 16, __half,
                           wmma::row_major> af[2];
            wmma::fragment<wmma::matrix_b, 16, 16, 16, __half,
                           wmma::row_major> bf[4];
#pragma unroll
            for (int i = 0; i < 2; i++)
                wmma::load_matrix_sync(af[i],
                    gW + (mw * 32 + i * 16) * CIN + cc * 128 + ks * 16, CIN);
#pragma unroll
            for (int j = 0; j < 4; j++)
                wmma::load_matrix_sync(bf[j],
                    Bsh + ks * 16 * BLDH + nw * 64 + j * 16, BLDH);
#pragma unroll
            for (int i = 0; i < 2; i++)
#pragma unroll
                for (int j = 0; j < 4; j++)
                    wmma::mma_sync(acc[i][j], af[i], bf[j], acc[i][j]);
        }
    }
    __syncthreads();

    // ---- epilogue: two n-waves through smem ----
    if (ASM) {
        if (tid < 54)   sms[tid]   = __ldg(ms + tid);
        if (tid < OUTC) sbias[tid] = __ldg(bias + tid);
    }

    int erow = tid >> 1;                 // 0..127
    int eoff = (tid & 1) * 32;
    float s = 0.f, s2 = 0.f;

#pragma unroll
    for (int wave = 0; wave < 2; wave++) {
        if (nw == wave) {
#pragma unroll
            for (int i = 0; i < 2; i++)
#pragma unroll
                for (int j = 0; j < 4; j++)
                    wmma::store_matrix_sync(
                        Dsm + (mw * 32 + i * 16) * DLD + j * 16,
                        acc[i][j], DLD, wmma::mem_row_major);
        }
        __syncthreads();
        if (!ASM) {
            float* yp = Y + b * C_ * K_ + erow * K_ + n0 + wave * 64 + eoff;
            const float* sp = Dsm + erow * DLD + eoff;
#pragma unroll
            for (int q = 0; q < 8; q++) {
                float4 v = *reinterpret_cast<const float4*>(sp + q * 4);
                *reinterpret_cast<float4*>(yp + q * 4) = v;
                if (STATS) {
                    s += v.x + v.y + v.z + v.w;
                    s2 = fmaf(v.x, v.x, s2); s2 = fmaf(v.y, v.y, s2);
                    s2 = fmaf(v.z, v.z, s2); s2 = fmaf(v.w, v.w, s2);
                }
            }
        } else {
            // fused 183-channel output assembly; Y == out base pointer
            int kbase = n0 + wave * 64;
            float* op = Y + ((size_t)b * K_ + kbase) * OCH;
            for (int e = tid; e < 64 * OCH; e += 256) {
                int kk = e / OCH;
                int ch = e - kk * OCH;
                int o;
                float scale = 1.f, add = 0.f;
                if (ch < 27) {               // center(+xyz), hs, hrn
                    o = ch;
                    if (ch < 3) add = xyz[((size_t)b * K_ + kbase + kk) * 3 + ch];
                } else if (ch < 39) {        // hr = hrn * pi/12
                    o = ch - 12;
                    scale = 0.26179938779914943f;
                } else if (ch < 111) {       // ss, srn
                    o = ch - 12;
                } else if (ch < 165) {       // sr = srn * mean_size
                    o = ch - 66;
                    scale = sms[ch - 111];
                } else {                     // sem
                    o = ch - 66;
                }
                op[e] = (Dsm[o * DLD + kk] + sbias[o]) * scale + add;
            }
        }
        __syncthreads();
    }

    if (STATS) {
        s  += __shfl_xor_sync(0xffffffffu, s, 1);
        s2 += __shfl_xor_sync(0xffffffffu, s2, 1);
        if ((tid & 1) == 0) {
            atomicAdd(&sS[erow], s);
            atomicAdd(&sS2[erow], s2);
        }
    }
}

// ===========================================================================
extern "C" void kernel_launch(void* const* d_in, const int* in_sizes, int n_in,
                              void* d_out, int out_size) {
    (void)in_sizes; (void)n_in; (void)out_size;
    const float* xyz      = (const float*)d_in[0];
    const float* features = (const float*)d_in[1];
    const float* rn       = (const float*)d_in[2];
    const float* gt       = (const float*)d_in[3];
    const int*   pred     = (const int*)d_in[4];   // int32
    const float* W1 = (const float*)d_in[5];
    const float* g1 = (const float*)d_in[7];
    const float* be1 = (const float*)d_in[8];
    const float* W2 = (const float*)d_in[9];
    const float* g2 = (const float*)d_in[11];
    const float* be2 = (const float*)d_in[12];
    const float* W3 = (const float*)d_in[13];
    const float* b3 = (const float*)d_in[14];
    const float* ms = (const float*)d_in[15];
    float* out = (float*)d_out;

    const int OFF_IDX = B_ * K_ * OCH;
    const int OFF_SUM = OFF_IDX + B_ * K_;
    const int OFF_LBL = OFF_SUM + B_;

    float *p_net1, *p_net2, *p_s, *p_s2;
    __half *p_W1h, *p_W2h, *p_W3h;
    cudaGetSymbolAddress((void**)&p_net1, g_net1);
    cudaGetSymbolAddress((void**)&p_net2, g_net2);
    cudaGetSymbolAddress((void**)&p_s,    g_s);
    cudaGetSymbolAddress((void**)&p_s2,   g_s2);
    cudaGetSymbolAddress((void**)&p_W1h,  g_W1h);
    cudaGetSymbolAddress((void**)&p_W2h,  g_W2h);
    cudaGetSymbolAddress((void**)&p_W3h,  g_W3h);

    prep_kernel<<<B_, K_>>>(xyz, gt, pred, W1, W2, W3,
                            out + OFF_LBL, out + OFF_IDX, out + OFF_SUM);

    dim3 gg(2, B_);
    // layer 1: concat input, stats -> g_s[0]
    wmma_gemm<256, 0, 1, 0><<<gg, 256>>>(p_W1h, nullptr, features, rn,
                                         nullptr, nullptr, nullptr, nullptr,
                                         p_net1, p_s, p_s2,
                                         nullptr, nullptr);
    // layer 2: in-kernel finalize from g_s[0], stats -> g_s[1]
    wmma_gemm<128, 1, 1, 0><<<gg, 256>>>(p_W2h, nullptr, p_net1, nullptr,
                                         g1, be1, p_s, p_s2,
                                         p_net2, p_s + C_, p_s2 + C_,
                                         nullptr, nullptr);
    // layer 3: in-kernel finalize from g_s[1], fused output assembly
    wmma_gemm<128, 1, 0, 1><<<gg, 256>>>(p_W3h, b3, p_net2, nullptr,
                                         g2, be2, p_s + C_, p_s2 + C_,
                                         out, nullptr, nullptr,
                                         xyz, ms);
}

// round 15
// speedup vs baseline: 1.0051x; 1.0051x over previous
#include <cuda_runtime.h>
#include <cuda_fp16.h>
#include <mma.h>
#include <cstdint>

using namespace nvcuda;

#define B_   256
#define K_   256
#define C_   128
#define KG_  64
#define OUTC 117
#define OCH  183

// scratch (allocation-free rule: __device__ globals)
__device__ float g_net1[B_ * C_ * K_];   // layer1 output, no bias (B,128,256)
__device__ float g_net2[B_ * C_ * K_];   // layer2 output, no bias
__device__ float g_s[2][C_];             // BN sum accumulators
__device__ float g_s2[2][C_];            // BN sum-of-squares accumulators
__device__ __half g_W1h[C_ * 2 * C_];    // fp16 W1 [128][256]
__device__ __half g_W2h[C_ * C_];        // fp16 W2 [128][128]
__device__ __half g_W3h[C_ * C_];        // fp16 W3 [128][128] (rows 117.. zero)

// ===========================================================================
// prep: weight fp16 conversion + objectness_label + get_index + zero stats
// grid = B_ (256 blocks), block = 256 threads; block b converts weight
// elements [b*256, b*256+256).
// ===========================================================================
__global__ void prep_kernel(const float* __restrict__ xyz,
                            const float* __restrict__ gt,
                            const int* __restrict__ pred,
                            const float* __restrict__ W1,
                            const float* __restrict__ W2,
                            const float* __restrict__ W3,
                            float* __restrict__ lbl,
                            float* __restrict__ idxo,
                            float* __restrict__ sum1) {
    int b = blockIdx.x, k = threadIdx.x;

    // ---- weight conversion: 1 element per thread ----
    {
        int i = b * 256 + k;
        if (i < 32768) {
            g_W1h[i] = __float2half_rn(W1[i]);
        } else if (i < 49152) {
            g_W2h[i - 32768] = __float2half_rn(W2[i - 32768]);
        } else {
            int j = i - 49152;
            int row = j >> 7;
            g_W3h[j] = (row < OUTC) ? __float2half_rn(W3[row * C_ + (j & 127)])
                                    : __float2half_rn(0.f);
        }
    }
    if (b == 0 && k < C_) {
        g_s[0][k] = 0.f; g_s[1][k] = 0.f;
        g_s2[0][k] = 0.f; g_s2[1][k] = 0.f;
    }

    // ---- label ----
    __shared__ float sg[KG_ * 3];
    if (k < KG_ * 3) sg[k] = gt[b * KG_ * 3 + k];
    __syncthreads();
    const float* p = xyz + (b * K_ + k) * 3;
    float x = p[0], y = p[1], z = p[2];
    float mn = 1e30f;
#pragma unroll 8
    for (int g = 0; g < KG_; g++) {
        float dx = x - sg[g * 3 + 0];
        float dy = y - sg[g * 3 + 1];
        float dz = z - sg[g * 3 + 2];
        mn = fminf(mn, dx * dx + dy * dy + dz * dz);
    }
    lbl[b * K_ + k] = (sqrtf(mn + 1e-6f) < 0.3f) ? 1.0f : 0.0f;

    // ---- index (pred is int32: JAX x64 disabled) ----
    int pv = pred[b * K_ + k];
    __shared__ int sc[K_];
    __shared__ int res[K_];
    sc[k] = pv;
    res[k] = k;
    __syncthreads();
    for (int off = 1; off < K_; off <<= 1) {
        int add = (k >= off) ? sc[k - off] : 0;
        __syncthreads();
        sc[k] += add;
        __syncthreads();
    }
    int num = sc[K_ - 1];
    int excl = sc[k] - pv;
    if (pv == 1) res[excl] = k;
    __syncthreads();
    idxo[b * K_ + k] = (float)((k < num) ? res[k] : k);
    if (k == 0) sum1[b] = (float)num;
}

// ===========================================================================
// wmma fp16 GEMM (fp32 accum): Y[b,m,n] = sum_c W[m,c]*X[b,c,n]
// (no bias in GEMM1/2 — BN cancels channel shifts exactly; b3 applied in ASM)
// FULL-K staging: Bsh holds a 128x128 B tile (one chunk); CIN=256 runs two
// chunks (chunk0 = X0/features, chunk1 = X1/rn). One sync pair per chunk;
// mma phase is 8 uninterrupted k-steps. A frags from global fp16 W (L1).
// FIN  : compute folded BN (a,d) per-CTA from g_s/g_s2 at kernel start.
// STATS: fused per-channel sum/sum^2 via shfl + atomics.
// ASM  : fuse 183-channel output assembly (bias b3 + scale + xyz).
// grid = (2 n-halves, B_), 256 threads (8 warps), warp tile 32x64, 2 CTA/SM.
// ===========================================================================
#define BLDH 136   // Bs leading dim in halves (272B rows; conflict-light)
#define DLD  68
// smem: Bsh 128*136*2 = 34816 B (aliased by Dsm 128*68*4 = 34816 B)
//       sA 512 B | sD 512 B | sms 216+ | sbias 468 -> total 36544
#define SMEM_BYTES 36544

template <int CIN, int FIN, int STATS, int ASM>
__global__ void __launch_bounds__(256, 2)
wmma_gemm(const __half* __restrict__ gW, const float* __restrict__ bias,
          const float* __restrict__ X0, const float* __restrict__ X1,
          const float* __restrict__ gam, const float* __restrict__ bet,
          const float* __restrict__ inS, const float* __restrict__ inS2,
          float* __restrict__ Y,
          float* __restrict__ sS, float* __restrict__ sS2,
          const float* __restrict__ xyz, const float* __restrict__ ms) {
    __shared__ __align__(16) char smbuf[SMEM_BYTES];
    __half* Bsh = reinterpret_cast<__half*>(smbuf);        // [128][BLDH]
    float*  Dsm = reinterpret_cast<float*>(smbuf);         // reused [128][DLD]
    float*  sA    = reinterpret_cast<float*>(smbuf + 34816);  // [128]
    float*  sD    = reinterpret_cast<float*>(smbuf + 35328);  // [128]
    float*  sms   = reinterpret_cast<float*>(smbuf + 35840);  // [54]
    float*  sbias = reinterpret_cast<float*>(smbuf + 36056);  // [117]

    int tid = threadIdx.x;
    int w = tid >> 5;
    int b = blockIdx.y;
    int n0 = blockIdx.x * 128;

    int mw = w >> 1;      // 0..3 -> m offset mw*32
    int nw = w & 1;       // 0..1 -> n offset nw*64

    // ---- in-kernel BN finalize: (a,d) from producer stats ----
    if (FIN) {
        if (tid < C_) {
            const float invN = 1.0f / (B_ * K_);
            float mean = inS[tid] * invN;
            float var = inS2[tid] * invN - mean * mean;
            float rstd = rsqrtf(var + 1e-5f);
            float av = rstd * __ldg(gam + tid);
            sA[tid] = av;
            sD[tid] = __ldg(bet + tid) - mean * av;
        }
        __syncthreads();
    }

    wmma::fragment<wmma::accumulator, 16, 16, 16, float> acc[2][4];
#pragma unroll
    for (int i = 0; i < 2; i++)
#pragma unroll
        for (int j = 0; j < 4; j++)
            wmma::fill_fragment(acc[i][j], 0.f);

    // B staging map: 128 rows, 2 threads/row, 64 floats each
    int brow = tid >> 1;
    int bhalf = (tid & 1) * 64;

    const int NCHUNK = CIN / 128;
#pragma unroll
    for (int cc = 0; cc < NCHUNK; cc++) {
        if (cc) __syncthreads();
        // ---- stage B chunk: X[cc*128+brow, n0+bhalf .. +64) ----
        {
            const float* base = (NCHUNK == 2)
                ? ((cc == 0) ? X0 : X1)   // concat along c
                : X0;
            const float* xp = base + b * C_ * K_ + brow * K_ + n0 + bhalf;
            __half* dst = Bsh + brow * BLDH + bhalf;
            float av = 0.f, dv = 0.f;
            if (FIN) { av = sA[brow]; dv = sD[brow]; }
#pragma unroll
            for (int g = 0; g < 2; g++) {          // 2 groups of 32 floats
                float4 v[8];
#pragma unroll
                for (int q = 0; q < 8; q++)
                    v[q] = *reinterpret_cast<const float4*>(xp + g * 32 + q * 4);
                __align__(16) __half2 h[16];
#pragma unroll
                for (int q = 0; q < 8; q++) {
                    if (FIN) {
                        v[q].x = fmaxf(fmaf(v[q].x, av, dv), 0.f);
                        v[q].y = fmaxf(fmaf(v[q].y, av, dv), 0.f);
                        v[q].z = fmaxf(fmaf(v[q].z, av, dv), 0.f);
                        v[q].w = fmaxf(fmaf(v[q].w, av, dv), 0.f);
                    }
                    h[2 * q]     = __floats2half2_rn(v[q].x, v[q].y);
                    h[2 * q + 1] = __floats2half2_rn(v[q].z, v[q].w);
                }
                uint4* db = reinterpret_cast<uint4*>(dst + g * 32);
                const uint4* sb = reinterpret_cast<const uint4*>(h);
#pragma unroll
                for (int r = 0; r < 4; r++) db[r] = sb[r];
            }
        }
        __syncthreads();

        // ---- one long mma phase: 8 k-steps ----
#pragma unroll
        for (int ks = 0; ks < 8; ks++) {
            wmma::fragment<wmma::matrix_a, 16, 16, 16, __half,
                           wmma::row_major> af[2];
            wmma::fragment<wmma::matrix_b, 16, 16, 16, __half,
                           wmma::row_major> bf[4];
#pragma unroll
            for (int i = 0; i < 2; i++)
                wmma::load_matrix_sync(af[i],
                    gW + (mw * 32 + i * 16) * CIN + cc * 128 + ks * 16, CIN);
#pragma unroll
            for (int j = 0; j < 4; j++)
                wmma::load_matrix_sync(bf[j],
                    Bsh + ks * 16 * BLDH + nw * 64 + j * 16, BLDH);
#pragma unroll
            for (int i = 0; i < 2; i++)
#pragma unroll
                for (int j = 0; j < 4; j++)
                    wmma::mma_sync(acc[i][j], af[i], bf[j], acc[i][j]);
        }
    }
    __syncthreads();

    // ---- epilogue: two n-waves through smem ----
    if (ASM) {
        if (tid < 54)   sms[tid]   = __ldg(ms + tid);
        if (tid < OUTC) sbias[tid] = __ldg(bias + tid);
    }

    int erow = tid >> 1;                 // 0..127
    int eoff = (tid & 1) * 32;
    float s = 0.f, s2 = 0.f;

#pragma unroll
    for (int wave = 0; wave < 2; wave++) {
        if (nw == wave) {
#pragma unroll
            for (int i = 0; i < 2; i++)
#pragma unroll
                for (int j = 0; j < 4; j++)
                    wmma::store_matrix_sync(
                        Dsm + (mw * 32 + i * 16) * DLD + j * 16,
                        acc[i][j], DLD, wmma::mem_row_major);
        }
        __syncthreads();
        if (!ASM) {
            float* yp = Y + b * C_ * K_ + erow * K_ + n0 + wave * 64 + eoff;
            const float* sp = Dsm + erow * DLD + eoff;
#pragma unroll
            for (int q = 0; q < 8; q++) {
                float4 v = *reinterpret_cast<const float4*>(sp + q * 4);
                *reinterpret_cast<float4*>(yp + q * 4) = v;
                if (STATS) {
                    s += v.x + v.y + v.z + v.w;
                    s2 = fmaf(v.x, v.x, s2); s2 = fmaf(v.y, v.y, s2);
                    s2 = fmaf(v.z, v.z, s2); s2 = fmaf(v.w, v.w, s2);
                }
            }
        } else {
            // fused 183-channel output assembly; Y == out base pointer
            int kbase = n0 + wave * 64;
            float* op = Y + ((size_t)b * K_ + kbase) * OCH;
            for (int e = tid; e < 64 * OCH; e += 256) {
                int kk = e / OCH;
                int ch = e - kk * OCH;
                int o;
                float scale = 1.f, add = 0.f;
                if (ch < 27) {               // center(+xyz), hs, hrn
                    o = ch;
                    if (ch < 3) add = xyz[((size_t)b * K_ + kbase + kk) * 3 + ch];
                } else if (ch < 39) {        // hr = hrn * pi/12
                    o = ch - 12;
                    scale = 0.26179938779914943f;
                } else if (ch < 111) {       // ss, srn
                    o = ch - 12;
                } else if (ch < 165) {       // sr = srn * mean_size
                    o = ch - 66;
                    scale = sms[ch - 111];
                } else {                     // sem
                    o = ch - 66;
                }
                op[e] = (Dsm[o * DLD + kk] + sbias[o]) * scale + add;
            }
        }
        __syncthreads();
    }

    if (STATS) {
        s  += __shfl_xor_sync(0xffffffffu, s, 1);
        s2 += __shfl_xor_sync(0xffffffffu, s2, 1);
        if ((tid & 1) == 0) {
            atomicAdd(&sS[erow], s);
            atomicAdd(&sS2[erow], s2);
        }
    }
}

// ===========================================================================
extern "C" void kernel_launch(void* const* d_in, const int* in_sizes, int n_in,
                              void* d_out, int out_size) {
    (void)in_sizes; (void)n_in; (void)out_size;
    const float* xyz      = (const float*)d_in[0];
    const float* features = (const float*)d_in[1];
    const float* rn       = (const float*)d_in[2];
    const float* gt       = (const float*)d_in[3];
    const int*   pred     = (const int*)d_in[4];   // int32
    const float* W1 = (const float*)d_in[5];
    const float* g1 = (const float*)d_in[7];
    const float* be1 = (const float*)d_in[8];
    const float* W2 = (const float*)d_in[9];
    const float* g2 = (const float*)d_in[11];
    const float* be2 = (const float*)d_in[12];
    const float* W3 = (const float*)d_in[13];
    const float* b3 = (const float*)d_in[14];
    const float* ms = (const float*)d_in[15];
    float* out = (float*)d_out;

    const int OFF_IDX = B_ * K_ * OCH;
    const int OFF_SUM = OFF_IDX + B_ * K_;
    const int OFF_LBL = OFF_SUM + B_;

    float *p_net1, *p_net2, *p_s, *p_s2;
    __half *p_W1h, *p_W2h, *p_W3h;
    cudaGetSymbolAddress((void**)&p_net1, g_net1);
    cudaGetSymbolAddress((void**)&p_net2, g_net2);
    cudaGetSymbolAddress((void**)&p_s,    g_s);
    cudaGetSymbolAddress((void**)&p_s2,   g_s2);
    cudaGetSymbolAddress((void**)&p_W1h,  g_W1h);
    cudaGetSymbolAddress((void**)&p_W2h,  g_W2h);
    cudaGetSymbolAddress((void**)&p_W3h,  g_W3h);

    prep_kernel<<<B_, K_>>>(xyz, gt, pred, W1, W2, W3,
                            out + OFF_LBL, out + OFF_IDX, out + OFF_SUM);

    dim3 gg(2, B_);
    // layer 1: concat input, stats -> g_s[0]
    wmma_gemm<256, 0, 1, 0><<<gg, 256>>>(p_W1h, nullptr, features, rn,
                                         nullptr, nullptr, nullptr, nullptr,
                                         p_net1, p_s, p_s2,
                                         nullptr, nullptr);
    // layer 2: in-kernel finalize from g_s[0], stats -> g_s[1]
    wmma_gemm<128, 1, 1, 0><<<gg, 256>>>(p_W2h, nullptr, p_net1, nullptr,
                                         g1, be1, p_s, p_s2,
                                         p_net2, p_s + C_, p_s2 + C_,
                                         nullptr, nullptr);
    // layer 3: in-kernel finalize from g_s[1], fused output assembly
    wmma_gemm<128, 1, 0, 1><<<gg, 256>>>(p_W3h, b3, p_net2, nullptr,
                                         g2, be2, p_s + C_, p_s2 + C_,
                                         out, nullptr, nullptr,
                                         xyz, ms);
}

// round 16
// speedup vs baseline: 1.1594x; 1.1535x over previous
#include <cuda_runtime.h>
#include <cuda_fp16.h>
#include <mma.h>
#include <cstdint>

using namespace nvcuda;

#define B_   256
#define K_   256
#define C_   128
#define KG_  64
#define OUTC 117
#define OCH  183

// scratch (allocation-free rule: __device__ globals)
__device__ float g_net1[B_ * C_ * K_];   // layer1 output, no bias (B,128,256)
__device__ float g_net2[B_ * C_ * K_];   // layer2 output, no bias
__device__ float g_s[2][C_];             // BN sum accumulators
__device__ float g_s2[2][C_];            // BN sum-of-squares accumulators
__device__ __half g_W1h[C_ * 2 * C_];    // fp16 W1 [128][256]
__device__ __half g_W2h[C_ * C_];        // fp16 W2 [128][128]
__device__ __half g_W3h[C_ * C_];        // fp16 W3 [128][128] (rows 117.. zero)

// ===========================================================================
// prep: weight fp16 conversion + objectness_label + get_index + zero stats
// ===========================================================================
__global__ void prep_kernel(const float* __restrict__ xyz,
                            const float* __restrict__ gt,
                            const int* __restrict__ pred,
                            const float* __restrict__ W1,
                            const float* __restrict__ W2,
                            const float* __restrict__ W3,
                            float* __restrict__ lbl,
                            float* __restrict__ idxo,
                            float* __restrict__ sum1) {
    int b = blockIdx.x, k = threadIdx.x;

    // ---- weight conversion: 1 element per thread ----
    {
        int i = b * 256 + k;
        if (i < 32768) {
            g_W1h[i] = __float2half_rn(W1[i]);
        } else if (i < 49152) {
            g_W2h[i - 32768] = __float2half_rn(W2[i - 32768]);
        } else {
            int j = i - 49152;
            int row = j >> 7;
            g_W3h[j] = (row < OUTC) ? __float2half_rn(W3[row * C_ + (j & 127)])
                                    : __float2half_rn(0.f);
        }
    }
    if (b == 0 && k < C_) {
        g_s[0][k] = 0.f; g_s[1][k] = 0.f;
        g_s2[0][k] = 0.f; g_s2[1][k] = 0.f;
    }

    // ---- label ----
    __shared__ float sg[KG_ * 3];
    if (k < KG_ * 3) sg[k] = gt[b * KG_ * 3 + k];
    __syncthreads();
    const float* p = xyz + (b * K_ + k) * 3;
    float x = p[0], y = p[1], z = p[2];
    float mn = 1e30f;
#pragma unroll 8
    for (int g = 0; g < KG_; g++) {
        float dx = x - sg[g * 3 + 0];
        float dy = y - sg[g * 3 + 1];
        float dz = z - sg[g * 3 + 2];
        mn = fminf(mn, dx * dx + dy * dy + dz * dz);
    }
    lbl[b * K_ + k] = (sqrtf(mn + 1e-6f) < 0.3f) ? 1.0f : 0.0f;

    // ---- index (pred is int32: JAX x64 disabled) ----
    int pv = pred[b * K_ + k];
    __shared__ int sc[K_];
    __shared__ int res[K_];
    sc[k] = pv;
    res[k] = k;
    __syncthreads();
    for (int off = 1; off < K_; off <<= 1) {
        int add = (k >= off) ? sc[k - off] : 0;
        __syncthreads();
        sc[k] += add;
        __syncthreads();
    }
    int num = sc[K_ - 1];
    int excl = sc[k] - pv;
    if (pv == 1) res[excl] = k;
    __syncthreads();
    idxo[b * K_ + k] = (float)((k < num) ? res[k] : k);
    if (k == 0) sum1[b] = (float)num;
}

// ===========================================================================
// wmma fp16 GEMM (fp32 accum): Y[b,m,n] = sum_c W[m,c]*X[b,c,n]
// FULL-K staging (Bsh = one 128x128 chunk; CIN=256 -> two chunks).
// A frags from global fp16 W (L1-resident). No bias in GEMM1/2 (BN cancels).
// FIN  : in-kernel BN finalize (a,d) from producer stats.
// STATS: fused per-channel sum/sum^2 via shfl + atomics.
// ASM  : fused 183-channel output assembly — table-driven channel mapping
//        (no div/branches), col-major D staging (conflict-free reads),
//        warp-per-k coalesced stores. bias b3 pre-folded into sadd[].
// grid = (2 n-halves, B_), 256 threads (8 warps), warp tile 32x64, 2 CTA/SM.
// ===========================================================================
#define BLDH 136   // Bs leading dim in halves (272B rows)
#define DLD  68    // row-major D staging ld (non-ASM)
#define DLDC 132   // col-major D staging ld (ASM): Dsm2[n][m], 64*132*4=33792B
// smem bytes: [0,34816) Bsh/Dsm/Dsm2 | sA 512 | sD 512 | so 736 | ssc 736 | sadd 736
#define SMEM_BYTES 38048

template <int CIN, int FIN, int STATS, int ASM>
__global__ void __launch_bounds__(256, 2)
wmma_gemm(const __half* __restrict__ gW, const float* __restrict__ bias,
          const float* __restrict__ X0, const float* __restrict__ X1,
          const float* __restrict__ gam, const float* __restrict__ bet,
          const float* __restrict__ inS, const float* __restrict__ inS2,
          float* __restrict__ Y,
          float* __restrict__ sS, float* __restrict__ sS2,
          const float* __restrict__ xyz, const float* __restrict__ ms) {
    __shared__ __align__(16) char smbuf[SMEM_BYTES];
    __half* Bsh  = reinterpret_cast<__half*>(smbuf);          // [128][BLDH]
    float*  Dsm  = reinterpret_cast<float*>(smbuf);           // [128][DLD] row-major
    float*  Dsm2 = reinterpret_cast<float*>(smbuf);           // [64][DLDC] col-major
    float*  sA   = reinterpret_cast<float*>(smbuf + 34816);   // [128]
    float*  sD   = reinterpret_cast<float*>(smbuf + 35328);   // [128]
    int*    so   = reinterpret_cast<int*>(smbuf + 35840);     // [183]
    float*  ssc  = reinterpret_cast<float*>(smbuf + 36576);   // [183]
    float*  sadd = reinterpret_cast<float*>(smbuf + 37312);   // [183]

    int tid = threadIdx.x;
    int w = tid >> 5;
    int lane = tid & 31;
    int b = blockIdx.y;
    int n0 = blockIdx.x * 128;

    int mw = w >> 1;      // 0..3 -> m offset mw*32
    int nw = w & 1;       // 0..1 -> n offset nw*64

    // ---- in-kernel BN finalize: (a,d) from producer stats ----
    if (FIN) {
        if (tid < C_) {
            const float invN = 1.0f / (B_ * K_);
            float mean = inS[tid] * invN;
            float var = inS2[tid] * invN - mean * mean;
            float rstd = rsqrtf(var + 1e-5f);
            float av = rstd * __ldg(gam + tid);
            sA[tid] = av;
            sD[tid] = __ldg(bet + tid) - mean * av;
        }
        __syncthreads();
    }

    wmma::fragment<wmma::accumulator, 16, 16, 16, float> acc[2][4];
#pragma unroll
    for (int i = 0; i < 2; i++)
#pragma unroll
        for (int j = 0; j < 4; j++)
            wmma::fill_fragment(acc[i][j], 0.f);

    // B staging map: 128 rows, 2 threads/row, 64 floats each
    int brow = tid >> 1;
    int bhalf = (tid & 1) * 64;

    const int NCHUNK = CIN / 128;
#pragma unroll
    for (int cc = 0; cc < NCHUNK; cc++) {
        if (cc) __syncthreads();
        // ---- stage B chunk: X[cc*128+brow, n0+bhalf .. +64) ----
        {
            const float* base = (NCHUNK == 2) ? ((cc == 0) ? X0 : X1) : X0;
            const float* xp = base + b * C_ * K_ + brow * K_ + n0 + bhalf;
            __half* dst = Bsh + brow * BLDH + bhalf;
            float av = 0.f, dv = 0.f;
            if (FIN) { av = sA[brow]; dv = sD[brow]; }
#pragma unroll
            for (int g = 0; g < 2; g++) {          // 2 groups of 32 floats
                float4 v[8];
#pragma unroll
                for (int q = 0; q < 8; q++)
                    v[q] = *reinterpret_cast<const float4*>(xp + g * 32 + q * 4);
                __align__(16) __half2 h[16];
#pragma unroll
                for (int q = 0; q < 8; q++) {
                    if (FIN) {
                        v[q].x = fmaxf(fmaf(v[q].x, av, dv), 0.f);
                        v[q].y = fmaxf(fmaf(v[q].y, av, dv), 0.f);
                        v[q].z = fmaxf(fmaf(v[q].z, av, dv), 0.f);
                        v[q].w = fmaxf(fmaf(v[q].w, av, dv), 0.f);
                    }
                    h[2 * q]     = __floats2half2_rn(v[q].x, v[q].y);
                    h[2 * q + 1] = __floats2half2_rn(v[q].z, v[q].w);
                }
                uint4* db = reinterpret_cast<uint4*>(dst + g * 32);
                const uint4* sb = reinterpret_cast<const uint4*>(h);
#pragma unroll
                for (int r = 0; r < 4; r++) db[r] = sb[r];
            }
        }
        __syncthreads();

        // ---- one long mma phase: 8 k-steps ----
#pragma unroll
        for (int ks = 0; ks < 8; ks++) {
            wmma::fragment<wmma::matrix_a, 16, 16, 16, __half,
                           wmma::row_major> af[2];
            wmma::fragment<wmma::matrix_b, 16, 16, 16, __half,
                           wmma::row_major> bf[4];
#pragma unroll
            for (int i = 0; i < 2; i++)
                wmma::load_matrix_sync(af[i],
                    gW + (mw * 32 + i * 16) * CIN + cc * 128 + ks * 16, CIN);
#pragma unroll
            for (int j = 0; j < 4; j++)
                wmma::load_matrix_sync(bf[j],
                    Bsh + ks * 16 * BLDH + nw * 64 + j * 16, BLDH);
#pragma unroll
            for (int i = 0; i < 2; i++)
#pragma unroll
                for (int j = 0; j < 4; j++)
                    wmma::mma_sync(acc[i][j], af[i], bf[j], acc[i][j]);
        }
    }
    __syncthreads();

    // ---- ASM: precompute channel tables (once, before wave 0 sync) ----
    if (ASM && tid < OCH) {
        int ch = tid;
        int o;
        float scale = 1.f;
        if (ch < 27) {
            o = ch;
        } else if (ch < 39) {
            o = ch - 12;
            scale = 0.26179938779914943f;
        } else if (ch < 111) {
            o = ch - 12;
        } else if (ch < 165) {
            o = ch - 66;
            scale = __ldg(ms + ch - 111);
        } else {
            o = ch - 66;
        }
        so[ch] = o;
        ssc[ch] = scale;
        sadd[ch] = __ldg(bias + o) * scale;
    }

    int erow = tid >> 1;                 // 0..127
    int eoff = (tid & 1) * 32;
    float s = 0.f, s2 = 0.f;

#pragma unroll
    for (int wave = 0; wave < 2; wave++) {
        if (nw == wave) {
#pragma unroll
            for (int i = 0; i < 2; i++)
#pragma unroll
                for (int j = 0; j < 4; j++) {
                    if (!ASM)
                        wmma::store_matrix_sync(
                            Dsm + (mw * 32 + i * 16) * DLD + j * 16,
                            acc[i][j], DLD, wmma::mem_row_major);
                    else
                        wmma::store_matrix_sync(
                            Dsm2 + (j * 16) * DLDC + (mw * 32 + i * 16),
                            acc[i][j], DLDC, wmma::mem_col_major);
                }
        }
        __syncthreads();
        if (!ASM) {
            float* yp = Y + b * C_ * K_ + erow * K_ + n0 + wave * 64 + eoff;
            const float* sp = Dsm + erow * DLD + eoff;
#pragma unroll
            for (int q = 0; q < 8; q++) {
                float4 v = *reinterpret_cast<const float4*>(sp + q * 4);
                *reinterpret_cast<float4*>(yp + q * 4) = v;
                if (STATS) {
                    s += v.x + v.y + v.z + v.w;
                    s2 = fmaf(v.x, v.x, s2); s2 = fmaf(v.y, v.y, s2);
                    s2 = fmaf(v.z, v.z, s2); s2 = fmaf(v.w, v.w, s2);
                }
            }
        } else {
            // table-driven assembly: warp-per-k, lanes sweep channels
            int kbase = n0 + wave * 64;
#pragma unroll
            for (int kq = 0; kq < 8; kq++) {
                int kk = w + kq * 8;             // 0..63 within wave
                const float* drow = Dsm2 + kk * DLDC;
                size_t gk = (size_t)b * K_ + kbase + kk;
                float* op = Y + gk * OCH;
#pragma unroll
                for (int pass = 0; pass < 6; pass++) {
                    int ch = lane + pass * 32;
                    if (ch < OCH) {
                        float v = fmaf(drow[so[ch]], ssc[ch], sadd[ch]);
                        if (ch < 3) v += __ldg(xyz + gk * 3 + ch);
                        op[ch] = v;
                    }
                }
            }
        }
        __syncthreads();
    }

    if (STATS) {
        s  += __shfl_xor_sync(0xffffffffu, s, 1);
        s2 += __shfl_xor_sync(0xffffffffu, s2, 1);
        if ((tid & 1) == 0) {
            atomicAdd(&sS[erow], s);
            atomicAdd(&sS2[erow], s2);
        }
    }
}

// ===========================================================================
extern "C" void kernel_launch(void* const* d_in, const int* in_sizes, int n_in,
                              void* d_out, int out_size) {
    (void)in_sizes; (void)n_in; (void)out_size;
    const float* xyz      = (const float*)d_in[0];
    const float* features = (const float*)d_in[1];
    const float* rn       = (const float*)d_in[2];
    const float* gt       = (const float*)d_in[3];
    const int*   pred     = (const int*)d_in[4];   // int32
    const float* W1 = (const float*)d_in[5];
    const float* g1 = (const float*)d_in[7];
    const float* be1 = (const float*)d_in[8];
    const float* W2 = (const float*)d_in[9];
    const float* g2 = (const float*)d_in[11];
    const float* be2 = (const float*)d_in[12];
    const float* W3 = (const float*)d_in[13];
    const float* b3 = (const float*)d_in[14];
    const float* ms = (const float*)d_in[15];
    float* out = (float*)d_out;

    const int OFF_IDX = B_ * K_ * OCH;
    const int OFF_SUM = OFF_IDX + B_ * K_;
    const int OFF_LBL = OFF_SUM + B_;

    float *p_net1, *p_net2, *p_s, *p_s2;
    __half *p_W1h, *p_W2h, *p_W3h;
    cudaGetSymbolAddress((void**)&p_net1, g_net1);
    cudaGetSymbolAddress((void**)&p_net2, g_net2);
    cudaGetSymbolAddress((void**)&p_s,    g_s);
    cudaGetSymbolAddress((void**)&p_s2,   g_s2);
    cudaGetSymbolAddress((void**)&p_W1h,  g_W1h);
    cudaGetSymbolAddress((void**)&p_W2h,  g_W2h);
    cudaGetSymbolAddress((void**)&p_W3h,  g_W3h);

    prep_kernel<<<B_, K_>>>(xyz, gt, pred, W1, W2, W3,
                            out + OFF_LBL, out + OFF_IDX, out + OFF_SUM);

    dim3 gg(2, B_);
    // layer 1: concat input, stats -> g_s[0]
    wmma_gemm<256, 0, 1, 0><<<gg, 256>>>(p_W1h, nullptr, features, rn,
                                         nullptr, nullptr, nullptr, nullptr,
                                         p_net1, p_s, p_s2,
                                         nullptr, nullptr);
    // layer 2: in-kernel finalize from g_s[0], stats -> g_s[1]
    wmma_gemm<128, 1, 1, 0><<<gg, 256>>>(p_W2h, nullptr, p_net1, nullptr,
                                         g1, be1, p_s, p_s2,
                                         p_net2, p_s + C_, p_s2 + C_,
                                         nullptr, nullptr);
    // layer 3: in-kernel finalize from g_s[1], fused output assembly
    wmma_gemm<128, 1, 0, 1><<<gg, 256>>>(p_W3h, b3, p_net2, nullptr,
                                         g2, be2, p_s + C_, p_s2 + C_,
                                         out, nullptr, nullptr,
                                         xyz, ms);
}